// round 7
// baseline (speedup 1.0000x reference)
#include <cuda_runtime.h>
#include <math.h>

#define SEQ    4096
#define DMODEL 768
#define NHEAD  12
#define HDIM   64
#define FFDIM  3072
#define NLAYER 12
#define SCALE  0.125f

// ---------------- scratch (static device allocations only) ----------------
__device__ float g_h [SEQ * DMODEL];
__device__ float g_q [SEQ * DMODEL];
__device__ float g_k [SEQ * DMODEL];
__device__ float g_v [SEQ * DMODEL];
__device__ float g_kg[SEQ * DMODEL];
__device__ float g_vg[SEQ * DMODEL];
__device__ float g_ao[SEQ * DMODEL];
__device__ float g_y [SEQ * DMODEL];
__device__ float g_t [SEQ * FFDIM];
__device__ float g_qg[8 * DMODEL];

// ---------------- GEMM: C[M,N] = A[M,K] @ B[K,N] + bias, optional GELU ----
// 128x128 block tile, BK=8, 256 threads, 8x8 per-thread microtile.
template<int ACT>
__global__ __launch_bounds__(256) void gemm_k(
    const float* __restrict__ A, const float* __restrict__ B,
    const float* __restrict__ bias, float* __restrict__ C,
    int M, int N, int K)
{
    __shared__ __align__(16) float As[8][132];
    __shared__ __align__(16) float Bs[8][132];
    const int bm = blockIdx.y * 128;
    const int bn = blockIdx.x * 128;
    const int tid = threadIdx.x;
    const int tx = tid & 15;
    const int ty = tid >> 4;
    const int arow = tid >> 1;
    const int acol = (tid & 1) * 4;
    const int brow = tid >> 5;
    const int bcol = (tid & 31) * 4;
    const float* Ap = A + (size_t)(bm + arow) * K + acol;
    const float* Bp = B + (size_t)brow * N + bn + bcol;

    float acc[8][8];
#pragma unroll
    for (int i = 0; i < 8; i++)
#pragma unroll
        for (int j = 0; j < 8; j++) acc[i][j] = 0.f;

    for (int k0 = 0; k0 < K; k0 += 8) {
        float4 av = *(const float4*)(Ap + k0);
        float4 bv = *(const float4*)(Bp + (size_t)k0 * N);
        As[acol + 0][arow] = av.x;
        As[acol + 1][arow] = av.y;
        As[acol + 2][arow] = av.z;
        As[acol + 3][arow] = av.w;
        *(float4*)&Bs[brow][bcol] = bv;
        __syncthreads();
#pragma unroll
        for (int kk = 0; kk < 8; kk++) {
            float4 a0 = *(const float4*)&As[kk][ty * 8];
            float4 a1 = *(const float4*)&As[kk][ty * 8 + 4];
            float4 b0 = *(const float4*)&Bs[kk][tx * 8];
            float4 b1 = *(const float4*)&Bs[kk][tx * 8 + 4];
            float ra[8] = {a0.x, a0.y, a0.z, a0.w, a1.x, a1.y, a1.z, a1.w};
            float rb[8] = {b0.x, b0.y, b0.z, b0.w, b1.x, b1.y, b1.z, b1.w};
#pragma unroll
            for (int i = 0; i < 8; i++)
#pragma unroll
                for (int j = 0; j < 8; j++) acc[i][j] += ra[i] * rb[j];
        }
        __syncthreads();
    }
#pragma unroll
    for (int i = 0; i < 8; i++) {
        int row = bm + ty * 8 + i;
        float* cp = C + (size_t)row * N + bn + tx * 8;
#pragma unroll
        for (int j = 0; j < 8; j++) {
            float vv = acc[i][j] + bias[bn + tx * 8 + j];
            if (ACT == 1) {  // tanh-approx GELU (jax.nn.gelu default)
                float u = vv;
                float t3 = 0.7978845608028654f * (u + 0.044715f * u * u * u);
                vv = 0.5f * u * (1.0f + tanhf(t3));
            }
            cp[j] = vv;
        }
    }
}

// ---------------- small GEMM over the 8 global-token rows -----------------
// out[g, n] = h[g*512, :] @ Wm[:, n] + bias[n]   (K fixed at 768)
__global__ __launch_bounds__(128) void gemm_rows_k(
    const float* __restrict__ h, const float* __restrict__ Wm,
    const float* __restrict__ bias, float* __restrict__ out, int N)
{
    __shared__ float a[DMODEL];
    const int g = blockIdx.x;
    const int n = blockIdx.y * 128 + threadIdx.x;
    const float* hr = h + (size_t)(g * 512) * DMODEL;
    for (int i = threadIdx.x; i < DMODEL; i += 128) a[i] = hr[i];
    __syncthreads();
    float s0 = 0, s1 = 0, s2 = 0, s3 = 0;
    for (int kk = 0; kk < DMODEL; kk += 4) {
        s0 += a[kk + 0] * Wm[(size_t)(kk + 0) * N + n];
        s1 += a[kk + 1] * Wm[(size_t)(kk + 1) * N + n];
        s2 += a[kk + 2] * Wm[(size_t)(kk + 2) * N + n];
        s3 += a[kk + 3] * Wm[(size_t)(kk + 3) * N + n];
    }
    out[(size_t)g * N + n] = (s0 + s1) + (s2 + s3) + bias[n];
}

// ---------------- local (sliding-window + global-key) attention -----------
// One block per (chunk c, head). One thread per query. Online softmax.
// Joint softmax over [8 global keys, 513-wide local band] exactly as ref.
__global__ __launch_bounds__(256) void local_attn_k(
    const float* __restrict__ Q, const float* __restrict__ K,
    const float* __restrict__ V, float* __restrict__ O)
{
    const int c = blockIdx.x;       // 0..15
    const int hh = blockIdx.y;      // 0..11
    const int q = threadIdx.x;      // 0..255
    const int p = c * 256 + q;
    const int hoff = hh * HDIM;

    __shared__ __align__(16) float Ks[64][64];
    __shared__ __align__(16) float Vs[64][64];
    __shared__ float kg[8][64];
    __shared__ float vg[8][64];

    float qv[64];
    {
        const float* qr = Q + (size_t)p * DMODEL + hoff;
#pragma unroll
        for (int d = 0; d < 64; d++) qv[d] = qr[d] * SCALE;
    }
    {   // load global-position K/V rows (k/v at GPOS = g*512), 2 elems/thread
        int g = threadIdx.x >> 5;
        int d = threadIdx.x & 31;
        const float* kr = K + (size_t)(g * 512) * DMODEL + hoff;
        const float* vr = V + (size_t)(g * 512) * DMODEL + hoff;
        kg[g][d] = kr[d]; kg[g][d + 32] = kr[d + 32];
        vg[g][d] = vr[d]; vg[g][d + 32] = vr[d + 32];
    }
    __syncthreads();

    // global-key scores first (they seed the running max)
    float sg[8];
    float m = -1e30f;
#pragma unroll
    for (int g = 0; g < 8; g++) {
        float s0 = 0, s1 = 0, s2 = 0, s3 = 0;
#pragma unroll
        for (int d = 0; d < 64; d += 4) {
            s0 += qv[d + 0] * kg[g][d + 0];
            s1 += qv[d + 1] * kg[g][d + 1];
            s2 += qv[d + 2] * kg[g][d + 2];
            s3 += qv[d + 3] * kg[g][d + 3];
        }
        sg[g] = (s0 + s1) + (s2 + s3);
        m = fmaxf(m, sg[g]);
    }
    float l = 0.f;
    float acc[64];
#pragma unroll
    for (int d = 0; d < 64; d++) acc[d] = 0.f;
#pragma unroll
    for (int g = 0; g < 8; g++) {
        float pe = __expf(sg[g] - m);
        l += pe;
#pragma unroll
        for (int d = 0; d < 64; d++) acc[d] += pe * vg[g][d];
    }

    // valid local j range for this query: j in [q, q+512], kpos in [0,S)
    int jlo = q;
    int jhi = q + 512;
    const int base = c * 256 - 256;          // kpos = base + j
    if (base < 0) { int lim = -base; if (jlo < lim) jlo = lim; }
    { int lim = 4095 - base; if (jhi > lim) jhi = lim; }
    const int qw0 = q & ~31;                  // warp-uniform skip bound

    for (int t = 0; t < 12; t++) {
        const int jbase = t * 64;
        __syncthreads();
        {   // cooperative tile load: 64 keys x 64 dims of K and V
            int j  = threadIdx.x >> 2;
            int d0 = (threadIdx.x & 3) * 16;
            int kpos = base + jbase + j;
            float4* kd = (float4*)&Ks[j][d0];
            float4* vd = (float4*)&Vs[j][d0];
            if (kpos >= 0 && kpos < SEQ) {
                const float4* ks = (const float4*)(K + (size_t)kpos * DMODEL + hoff + d0);
                const float4* vs = (const float4*)(V + (size_t)kpos * DMODEL + hoff + d0);
#pragma unroll
                for (int u = 0; u < 4; u++) { kd[u] = ks[u]; vd[u] = vs[u]; }
            } else {
                float4 z = make_float4(0.f, 0.f, 0.f, 0.f);
#pragma unroll
                for (int u = 0; u < 4; u++) { kd[u] = z; vd[u] = z; }
            }
        }
        __syncthreads();
        // warp-uniform tile skip (window of any lane in warp: [qw0, qw0+543])
        if (jbase + 63 < qw0 || jbase > qw0 + 543) continue;

        for (int jj = 0; jj < 64; jj++) {    // uniform jj -> smem broadcast
            int jg = jbase + jj;
            float s0 = 0, s1 = 0, s2 = 0, s3 = 0;
#pragma unroll
            for (int d = 0; d < 64; d += 4) {
                s0 += qv[d + 0] * Ks[jj][d + 0];
                s1 += qv[d + 1] * Ks[jj][d + 1];
                s2 += qv[d + 2] * Ks[jj][d + 2];
                s3 += qv[d + 3] * Ks[jj][d + 3];
            }
            float s = (s0 + s1) + (s2 + s3);
            if (jg < jlo || jg > jhi) s = -1e30f;   // mask => exp underflows to 0
            if (s > m) {
                float corr = __expf(m - s);
                m = s;
                l *= corr;
#pragma unroll
                for (int d = 0; d < 64; d++) acc[d] *= corr;
            }
            float pe = __expf(s - m);
            l += pe;
#pragma unroll
            for (int d = 0; d < 64; d++) acc[d] += pe * Vs[jj][d];
        }
    }
    float inv = 1.0f / l;
    float* orow = O + (size_t)p * DMODEL + hoff;
#pragma unroll
    for (int d = 0; d < 64; d++) orow[d] = acc[d] * inv;
}

// ---------------- full attention for the 8 global tokens ------------------
// One block per (global g, head). Overwrites O rows at GPOS.
__global__ __launch_bounds__(256) void global_attn_k(
    const float* __restrict__ QG, const float* __restrict__ KG,
    const float* __restrict__ VG, float* __restrict__ O)
{
    const int g = blockIdx.x;
    const int hh = blockIdx.y;
    const int hoff = hh * HDIM;
    const int t = threadIdx.x;
    __shared__ float qv[64];
    __shared__ float sc[SEQ];
    __shared__ float red[256];
    if (t < 64) qv[t] = QG[g * DMODEL + hoff + t] * SCALE;
    __syncthreads();
    float lmax = -1e30f;
    for (int k = t; k < SEQ; k += 256) {
        const float4* kr = (const float4*)(KG + (size_t)k * DMODEL + hoff);
        float s0 = 0, s1 = 0, s2 = 0, s3 = 0;
#pragma unroll
        for (int d4 = 0; d4 < 16; d4++) {
            float4 kv = kr[d4];
            s0 += qv[d4 * 4 + 0] * kv.x;
            s1 += qv[d4 * 4 + 1] * kv.y;
            s2 += qv[d4 * 4 + 2] * kv.z;
            s3 += qv[d4 * 4 + 3] * kv.w;
        }
        float s = (s0 + s1) + (s2 + s3);
        sc[k] = s;
        lmax = fmaxf(lmax, s);
    }
    red[t] = lmax; __syncthreads();
    for (int st = 128; st > 0; st >>= 1) {
        if (t < st) red[t] = fmaxf(red[t], red[t + st]);
        __syncthreads();
    }
    float mx = red[0];
    __syncthreads();
    float lsum = 0.f;
    for (int k = t; k < SEQ; k += 256) {
        float e = __expf(sc[k] - mx);
        sc[k] = e;
        lsum += e;
    }
    red[t] = lsum; __syncthreads();
    for (int st = 128; st > 0; st >>= 1) {
        if (t < st) red[t] += red[t + st];
        __syncthreads();
    }
    float inv = 1.0f / red[0];
    __syncthreads();
    if (t < 64) {
        float a0 = 0, a1 = 0, a2 = 0, a3 = 0;
        for (int k = 0; k < SEQ; k += 4) {
            a0 += sc[k + 0] * VG[(size_t)(k + 0) * DMODEL + hoff + t];
            a1 += sc[k + 1] * VG[(size_t)(k + 1) * DMODEL + hoff + t];
            a2 += sc[k + 2] * VG[(size_t)(k + 2) * DMODEL + hoff + t];
            a3 += sc[k + 3] * VG[(size_t)(k + 3) * DMODEL + hoff + t];
        }
        O[(size_t)(g * 512) * DMODEL + hoff + t] = ((a0 + a1) + (a2 + a3)) * inv;
    }
}

// ---------------- LayerNorm helpers ---------------------------------------
__device__ __forceinline__ void block_ln(
    float* buf, float* red, const float* __restrict__ s,
    const float* __restrict__ b, float* __restrict__ out)
{
    const int t = threadIdx.x;
    float ls = 0.f;
    for (int i = t; i < DMODEL; i += 256) ls += buf[i];
    red[t] = ls; __syncthreads();
    for (int st = 128; st > 0; st >>= 1) {
        if (t < st) red[t] += red[t + st];
        __syncthreads();
    }
    float mean = red[0] * (1.0f / DMODEL);
    __syncthreads();
    float lv = 0.f;
    for (int i = t; i < DMODEL; i += 256) {
        float d = buf[i] - mean;
        lv += d * d;
    }
    red[t] = lv; __syncthreads();
    for (int st = 128; st > 0; st >>= 1) {
        if (t < st) red[t] += red[t + st];
        __syncthreads();
    }
    float inv = rsqrtf(red[0] * (1.0f / DMODEL) + 1e-5f);
    for (int i = t; i < DMODEL; i += 256)
        out[i] = (buf[i] - mean) * inv * s[i] + b[i];
}

__global__ __launch_bounds__(256) void embed_ln_k(
    const int* __restrict__ x, const float* __restrict__ we,
    const float* __restrict__ pe, const float* __restrict__ s,
    const float* __restrict__ b, float* __restrict__ h)
{
    const int p = blockIdx.x;
    const int w = p >> 9, off = p & 511;
    const int id = (off == 0) ? 0 : x[w * 511 + off - 1];
    __shared__ float buf[DMODEL];
    __shared__ float red[256];
    for (int i = threadIdx.x; i < DMODEL; i += 256)
        buf[i] = we[(size_t)id * DMODEL + i] + pe[(size_t)p * DMODEL + i];
    __syncthreads();
    block_ln(buf, red, s, b, h + (size_t)p * DMODEL);
}

__global__ __launch_bounds__(256) void add_ln_k(
    float* __restrict__ h, const float* __restrict__ y,
    const float* __restrict__ s, const float* __restrict__ b)
{
    const int p = blockIdx.x;
    __shared__ float buf[DMODEL];
    __shared__ float red[256];
    for (int i = threadIdx.x; i < DMODEL; i += 256)
        buf[i] = h[(size_t)p * DMODEL + i] + y[(size_t)p * DMODEL + i];
    __syncthreads();
    block_ln(buf, red, s, b, h + (size_t)p * DMODEL);
}

// ---------------- driver ---------------------------------------------------
extern "C" void kernel_launch(void* const* d_in, const int* in_sizes, int n_in,
                              void* d_out, int out_size)
{
    const int*   x    = (const int*)d_in[0];
    const float* we   = (const float*)d_in[1];
    const float* pe   = (const float*)d_in[2];
    const float* els  = (const float*)d_in[3];
    const float* elb  = (const float*)d_in[4];
    const float* Wq   = (const float*)d_in[5];
    const float* bq   = (const float*)d_in[6];
    const float* Wk   = (const float*)d_in[7];
    const float* bk   = (const float*)d_in[8];
    const float* Wv   = (const float*)d_in[9];
    const float* bv   = (const float*)d_in[10];
    const float* Wo   = (const float*)d_in[11];
    const float* bo   = (const float*)d_in[12];
    const float* Wqg  = (const float*)d_in[13];
    const float* bqg  = (const float*)d_in[14];
    const float* Wkg  = (const float*)d_in[15];
    const float* bkg  = (const float*)d_in[16];
    const float* Wvg  = (const float*)d_in[17];
    const float* bvg  = (const float*)d_in[18];
    const float* ln1s = (const float*)d_in[19];
    const float* ln1b = (const float*)d_in[20];
    const float* W1   = (const float*)d_in[21];
    const float* b1   = (const float*)d_in[22];
    const float* W2   = (const float*)d_in[23];
    const float* b2   = (const float*)d_in[24];
    const float* ln2s = (const float*)d_in[25];
    const float* ln2b = (const float*)d_in[26];
    const float* Wout = (const float*)d_in[27];
    const float* bout = (const float*)d_in[28];

    float *h, *q, *k, *v, *kg, *vg, *ao, *y, *tb, *qg;
    cudaGetSymbolAddress((void**)&h,  g_h);
    cudaGetSymbolAddress((void**)&q,  g_q);
    cudaGetSymbolAddress((void**)&k,  g_k);
    cudaGetSymbolAddress((void**)&v,  g_v);
    cudaGetSymbolAddress((void**)&kg, g_kg);
    cudaGetSymbolAddress((void**)&vg, g_vg);
    cudaGetSymbolAddress((void**)&ao, g_ao);
    cudaGetSymbolAddress((void**)&y,  g_y);
    cudaGetSymbolAddress((void**)&tb, g_t);
    cudaGetSymbolAddress((void**)&qg, g_qg);

    embed_ln_k<<<SEQ, 256>>>(x, we, pe, els, elb, h);

    dim3 gA(6, 32);    // N=768,  M=4096
    dim3 gF1(24, 32);  // N=3072, M=4096
    for (int l = 0; l < NLAYER; l++) {
        size_t wofs = (size_t)l * DMODEL * DMODEL;
        size_t bofs = (size_t)l * DMODEL;

        gemm_k<0><<<gA, 256>>>(h, Wq  + wofs, bq  + bofs, q,  SEQ, DMODEL, DMODEL);
        gemm_k<0><<<gA, 256>>>(h, Wk  + wofs, bk  + bofs, k,  SEQ, DMODEL, DMODEL);
        gemm_k<0><<<gA, 256>>>(h, Wv  + wofs, bv  + bofs, v,  SEQ, DMODEL, DMODEL);
        gemm_k<0><<<gA, 256>>>(h, Wkg + wofs, bkg + bofs, kg, SEQ, DMODEL, DMODEL);
        gemm_k<0><<<gA, 256>>>(h, Wvg + wofs, bvg + bofs, vg, SEQ, DMODEL, DMODEL);
        gemm_rows_k<<<dim3(8, 6), 128>>>(h, Wqg + wofs, bqg + bofs, qg, DMODEL);

        local_attn_k<<<dim3(16, 12), 256>>>(q, k, v, ao);
        global_attn_k<<<dim3(8, 12), 256>>>(qg, kg, vg, ao);

        gemm_k<0><<<gA, 256>>>(ao, Wo + wofs, bo + bofs, y, SEQ, DMODEL, DMODEL);
        add_ln_k<<<SEQ, 256>>>(h, y, ln1s + bofs, ln1b + bofs);

        gemm_k<1><<<gF1, 256>>>(h,  W1 + (size_t)l * DMODEL * FFDIM,
                                b1 + (size_t)l * FFDIM, tb, SEQ, FFDIM, DMODEL);
        gemm_k<0><<<gA, 256>>>(tb, W2 + (size_t)l * FFDIM * DMODEL,
                               b2 + bofs, y, SEQ, DMODEL, FFDIM);
        add_ln_k<<<SEQ, 256>>>(h, y, ln2s + bofs, ln2b + bofs);
    }

    gemm_rows_k<<<dim3(8, 1), 128>>>(h, Wout, bout, (float*)d_out, 128);
}

// round 10
// speedup vs baseline: 1.9626x; 1.9626x over previous
#include <cuda_runtime.h>
#include <math.h>
#include <stdint.h>

#define SEQ    4096
#define DMODEL 768
#define NHEAD  12
#define HDIM   64
#define FFDIM  3072
#define NLAYER 12
#define SCALE  0.125f

// ---------------- scratch (static device allocations only) ----------------
__device__ float g_h [SEQ * DMODEL];
__device__ float g_q [SEQ * DMODEL];
__device__ float g_k [SEQ * DMODEL];
__device__ float g_v [SEQ * DMODEL];
__device__ float g_kg[SEQ * DMODEL];
__device__ float g_vg[SEQ * DMODEL];
__device__ float g_ao[SEQ * DMODEL];
__device__ float g_y [SEQ * DMODEL];
__device__ float g_t [SEQ * FFDIM];
__device__ float g_qg[8 * DMODEL];

// ---------------- tf32 helpers --------------------------------------------
__device__ __forceinline__ uint32_t f2tf32(float x) {
    uint32_t r;
    asm("cvt.rna.tf32.f32 %0, %1;" : "=r"(r) : "f"(x));
    return r;
}

__device__ __forceinline__ void mma_tf32(float d[4], const uint32_t a[4],
                                         const uint32_t b[2]) {
    asm volatile(
        "mma.sync.aligned.m16n8k8.row.col.f32.tf32.tf32.f32 "
        "{%0,%1,%2,%3}, {%4,%5,%6,%7}, {%8,%9}, {%0,%1,%2,%3};\n"
        : "+f"(d[0]), "+f"(d[1]), "+f"(d[2]), "+f"(d[3])
        : "r"(a[0]), "r"(a[1]), "r"(a[2]), "r"(a[3]), "r"(b[0]), "r"(b[1]));
}

__device__ __forceinline__ float gelu_f(float u) {
    float t3 = 0.7978845608028654f * (u + 0.044715f * u * u * u);
    return 0.5f * u * (1.0f + tanhf(t3));
}

// ---------------- tensor-core GEMM body -----------------------------------
// C[M,N] = A[M,K] @ B[K,N] + bias, optional GELU. Tile 128x128, BK=16,
// 256 threads / 8 warps, warp tile 64x32 (2x4 warp grid), m16n8k8 tf32 MMA.
// smem row stride 136 floats => fragment LDS bank = 8*k + m (conflict-free).
template<int ACT>
__device__ __forceinline__ void gemm_body(
    const float* __restrict__ A, const float* __restrict__ B,
    const float* __restrict__ bias, float* __restrict__ C,
    int M, int N, int K)
{
    __shared__ __align__(16) uint32_t As[2][16][136];
    __shared__ __align__(16) uint32_t Bs[2][16][136];

    const int bm  = blockIdx.y * 128;
    const int bn  = blockIdx.x * 128;
    const int tid = threadIdx.x;
    const int lane = tid & 31;
    const int wid  = tid >> 5;
    const int wm = wid & 1;    // 0..1  -> 64-row slab
    const int wn = wid >> 1;   // 0..3  -> 32-col slab
    const int lk = lane & 3;
    const int lm = lane >> 2;

    // cooperative load assignment
    const int arow = tid >> 1;          // 0..127
    const int akb  = (tid & 1) * 8;     // 0 | 8
    const int brow = tid >> 4;          // 0..15
    const int bcol = (tid & 15) * 8;    // 0..120

    const float* Ap = A + (size_t)(bm + arow) * K + akb;
    const float* Bp = B + (size_t)brow * N + bn + bcol;

    float acc[4][4][4];
#pragma unroll
    for (int mi = 0; mi < 4; mi++)
#pragma unroll
        for (int ni = 0; ni < 4; ni++)
#pragma unroll
            for (int u = 0; u < 4; u++) acc[mi][ni][u] = 0.f;

    const int nIter = K >> 4;

    float4 ra0, ra1, rb0, rb1;
    ra0 = *(const float4*)(Ap);
    ra1 = *(const float4*)(Ap + 4);
    rb0 = *(const float4*)(Bp);
    rb1 = *(const float4*)(Bp + 4);

    // store tile 0 into buffer 0
    {
        As[0][akb + 0][arow] = f2tf32(ra0.x);
        As[0][akb + 1][arow] = f2tf32(ra0.y);
        As[0][akb + 2][arow] = f2tf32(ra0.z);
        As[0][akb + 3][arow] = f2tf32(ra0.w);
        As[0][akb + 4][arow] = f2tf32(ra1.x);
        As[0][akb + 5][arow] = f2tf32(ra1.y);
        As[0][akb + 6][arow] = f2tf32(ra1.z);
        As[0][akb + 7][arow] = f2tf32(ra1.w);
        uint4 w0 = make_uint4(f2tf32(rb0.x), f2tf32(rb0.y), f2tf32(rb0.z), f2tf32(rb0.w));
        uint4 w1 = make_uint4(f2tf32(rb1.x), f2tf32(rb1.y), f2tf32(rb1.z), f2tf32(rb1.w));
        *(uint4*)&Bs[0][brow][bcol]     = w0;
        *(uint4*)&Bs[0][brow][bcol + 4] = w1;
    }
    __syncthreads();

    int buf = 0;
    for (int it = 0; it < nIter; ++it) {
        if (it + 1 < nIter) {
            const float* An = Ap + (it + 1) * 16;
            const float* Bn = Bp + (size_t)(it + 1) * 16 * N;
            ra0 = *(const float4*)(An);
            ra1 = *(const float4*)(An + 4);
            rb0 = *(const float4*)(Bn);
            rb1 = *(const float4*)(Bn + 4);
        }
#pragma unroll
        for (int ks = 0; ks < 2; ks++) {
            const int kk = ks * 8 + lk;
            uint32_t af[4][4], bf[4][2];
#pragma unroll
            for (int mi = 0; mi < 4; mi++) {
                int r = wm * 64 + mi * 16 + lm;
                af[mi][0] = As[buf][kk][r];
                af[mi][1] = As[buf][kk][r + 8];
                af[mi][2] = As[buf][kk + 4][r];
                af[mi][3] = As[buf][kk + 4][r + 8];
            }
#pragma unroll
            for (int ni = 0; ni < 4; ni++) {
                int cc = wn * 32 + ni * 8 + lm;
                bf[ni][0] = Bs[buf][kk][cc];
                bf[ni][1] = Bs[buf][kk + 4][cc];
            }
#pragma unroll
            for (int mi = 0; mi < 4; mi++)
#pragma unroll
                for (int ni = 0; ni < 4; ni++)
                    mma_tf32(acc[mi][ni], af[mi], bf[ni]);
        }
        if (it + 1 < nIter) {
            int nb = buf ^ 1;
            As[nb][akb + 0][arow] = f2tf32(ra0.x);
            As[nb][akb + 1][arow] = f2tf32(ra0.y);
            As[nb][akb + 2][arow] = f2tf32(ra0.z);
            As[nb][akb + 3][arow] = f2tf32(ra0.w);
            As[nb][akb + 4][arow] = f2tf32(ra1.x);
            As[nb][akb + 5][arow] = f2tf32(ra1.y);
            As[nb][akb + 6][arow] = f2tf32(ra1.z);
            As[nb][akb + 7][arow] = f2tf32(ra1.w);
            uint4 w0 = make_uint4(f2tf32(rb0.x), f2tf32(rb0.y), f2tf32(rb0.z), f2tf32(rb0.w));
            uint4 w1 = make_uint4(f2tf32(rb1.x), f2tf32(rb1.y), f2tf32(rb1.z), f2tf32(rb1.w));
            *(uint4*)&Bs[nb][brow][bcol]     = w0;
            *(uint4*)&Bs[nb][brow][bcol + 4] = w1;
            __syncthreads();
            buf = nb;
        }
    }

    // epilogue
#pragma unroll
    for (int mi = 0; mi < 4; mi++) {
        int row0 = bm + wm * 64 + mi * 16 + (lane >> 2);
#pragma unroll
        for (int ni = 0; ni < 4; ni++) {
            int col = bn + wn * 32 + ni * 8 + (lane & 3) * 2;
            float bb0 = bias[col], bb1 = bias[col + 1];
            float v0 = acc[mi][ni][0] + bb0;
            float v1 = acc[mi][ni][1] + bb1;
            float v2 = acc[mi][ni][2] + bb0;
            float v3 = acc[mi][ni][3] + bb1;
            if (ACT == 1) { v0 = gelu_f(v0); v1 = gelu_f(v1); v2 = gelu_f(v2); v3 = gelu_f(v3); }
            *(float2*)(C + (size_t)row0 * N + col)       = make_float2(v0, v1);
            *(float2*)(C + (size_t)(row0 + 8) * N + col) = make_float2(v2, v3);
        }
    }
}

template<int ACT>
__global__ __launch_bounds__(256, 2) void gemm_tf32_k(
    const float* __restrict__ A, const float* __restrict__ B,
    const float* __restrict__ bias, float* __restrict__ C,
    int M, int N, int K)
{
    gemm_body<ACT>(A, B, bias, C, M, N, K);
}

// fused QKV/Kg/Vg: same A, 5 weight/bias/out triples selected by blockIdx.z
struct Ptrs5 {
    const float* W[5];
    const float* b[5];
    float*       C[5];
};

__global__ __launch_bounds__(256, 2) void gemm_qkv5_k(
    const float* __restrict__ A, Ptrs5 p, int M, int N, int K)
{
    int z = blockIdx.z;
    gemm_body<0>(A, p.W[z], p.b[z], p.C[z], M, N, K);
}

// ---------------- small GEMM over the 8 global-token rows -----------------
__global__ __launch_bounds__(128) void gemm_rows_k(
    const float* __restrict__ h, const float* __restrict__ Wm,
    const float* __restrict__ bias, float* __restrict__ out, int N)
{
    __shared__ float a[DMODEL];
    const int g = blockIdx.x;
    const int n = blockIdx.y * 128 + threadIdx.x;
    const float* hr = h + (size_t)(g * 512) * DMODEL;
    for (int i = threadIdx.x; i < DMODEL; i += 128) a[i] = hr[i];
    __syncthreads();
    float s0 = 0, s1 = 0, s2 = 0, s3 = 0;
    for (int kk = 0; kk < DMODEL; kk += 4) {
        s0 += a[kk + 0] * Wm[(size_t)(kk + 0) * N + n];
        s1 += a[kk + 1] * Wm[(size_t)(kk + 1) * N + n];
        s2 += a[kk + 2] * Wm[(size_t)(kk + 2) * N + n];
        s3 += a[kk + 3] * Wm[(size_t)(kk + 3) * N + n];
    }
    out[(size_t)g * N + n] = (s0 + s1) + (s2 + s3) + bias[n];
}

// ---------------- local (sliding-window + global-key) attention -----------
__global__ __launch_bounds__(256) void local_attn_k(
    const float* __restrict__ Q, const float* __restrict__ K,
    const float* __restrict__ V, float* __restrict__ O)
{
    const int c = blockIdx.x;       // 0..15
    const int hh = blockIdx.y;      // 0..11
    const int q = threadIdx.x;      // 0..255
    const int p = c * 256 + q;
    const int hoff = hh * HDIM;

    __shared__ __align__(16) float Ks[64][64];
    __shared__ __align__(16) float Vs[64][64];
    __shared__ float kg[8][64];
    __shared__ float vg[8][64];

    float qv[64];
    {
        const float* qr = Q + (size_t)p * DMODEL + hoff;
#pragma unroll
        for (int d = 0; d < 64; d++) qv[d] = qr[d] * SCALE;
    }
    {
        int g = threadIdx.x >> 5;
        int d = threadIdx.x & 31;
        const float* kr = K + (size_t)(g * 512) * DMODEL + hoff;
        const float* vr = V + (size_t)(g * 512) * DMODEL + hoff;
        kg[g][d] = kr[d]; kg[g][d + 32] = kr[d + 32];
        vg[g][d] = vr[d]; vg[g][d + 32] = vr[d + 32];
    }
    __syncthreads();

    float sg[8];
    float m = -1e30f;
#pragma unroll
    for (int g = 0; g < 8; g++) {
        float s0 = 0, s1 = 0, s2 = 0, s3 = 0;
#pragma unroll
        for (int d = 0; d < 64; d += 4) {
            s0 += qv[d + 0] * kg[g][d + 0];
            s1 += qv[d + 1] * kg[g][d + 1];
            s2 += qv[d + 2] * kg[g][d + 2];
            s3 += qv[d + 3] * kg[g][d + 3];
        }
        sg[g] = (s0 + s1) + (s2 + s3);
        m = fmaxf(m, sg[g]);
    }
    float l = 0.f;
    float acc[64];
#pragma unroll
    for (int d = 0; d < 64; d++) acc[d] = 0.f;
#pragma unroll
    for (int g = 0; g < 8; g++) {
        float pe = __expf(sg[g] - m);
        l += pe;
#pragma unroll
        for (int d = 0; d < 64; d++) acc[d] += pe * vg[g][d];
    }

    int jlo = q;
    int jhi = q + 512;
    const int base = c * 256 - 256;
    if (base < 0) { int lim = -base; if (jlo < lim) jlo = lim; }
    { int lim = 4095 - base; if (jhi > lim) jhi = lim; }
    const int qw0 = q & ~31;

    for (int t = 0; t < 12; t++) {
        const int jbase = t * 64;
        __syncthreads();
        {
            int j  = threadIdx.x >> 2;
            int d0 = (threadIdx.x & 3) * 16;
            int kpos = base + jbase + j;
            float4* kd = (float4*)&Ks[j][d0];
            float4* vd = (float4*)&Vs[j][d0];
            if (kpos >= 0 && kpos < SEQ) {
                const float4* ks = (const float4*)(K + (size_t)kpos * DMODEL + hoff + d0);
                const float4* vs = (const float4*)(V + (size_t)kpos * DMODEL + hoff + d0);
#pragma unroll
                for (int u = 0; u < 4; u++) { kd[u] = ks[u]; vd[u] = vs[u]; }
            } else {
                float4 z = make_float4(0.f, 0.f, 0.f, 0.f);
#pragma unroll
                for (int u = 0; u < 4; u++) { kd[u] = z; vd[u] = z; }
            }
        }
        __syncthreads();
        if (jbase + 63 < qw0 || jbase > qw0 + 543) continue;

        for (int jj = 0; jj < 64; jj++) {
            int jg = jbase + jj;
            float s0 = 0, s1 = 0, s2 = 0, s3 = 0;
#pragma unroll
            for (int d = 0; d < 64; d += 4) {
                s0 += qv[d + 0] * Ks[jj][d + 0];
                s1 += qv[d + 1] * Ks[jj][d + 1];
                s2 += qv[d + 2] * Ks[jj][d + 2];
                s3 += qv[d + 3] * Ks[jj][d + 3];
            }
            float s = (s0 + s1) + (s2 + s3);
            if (jg < jlo || jg > jhi) s = -1e30f;
            if (s > m) {
                float corr = __expf(m - s);
                m = s;
                l *= corr;
#pragma unroll
                for (int d = 0; d < 64; d++) acc[d] *= corr;
            }
            float pe = __expf(s - m);
            l += pe;
#pragma unroll
            for (int d = 0; d < 64; d++) acc[d] += pe * Vs[jj][d];
        }
    }
    float inv = 1.0f / l;
    float* orow = O + (size_t)p * DMODEL + hoff;
#pragma unroll
    for (int d = 0; d < 64; d++) orow[d] = acc[d] * inv;
}

// ---------------- full attention for the 8 global tokens ------------------
__global__ __launch_bounds__(256) void global_attn_k(
    const float* __restrict__ QG, const float* __restrict__ KG,
    const float* __restrict__ VG, float* __restrict__ O)
{
    const int g = blockIdx.x;
    const int hh = blockIdx.y;
    const int hoff = hh * HDIM;
    const int t = threadIdx.x;
    __shared__ float qv[64];
    __shared__ float sc[SEQ];
    __shared__ float red[256];
    if (t < 64) qv[t] = QG[g * DMODEL + hoff + t] * SCALE;
    __syncthreads();
    float lmax = -1e30f;
    for (int k = t; k < SEQ; k += 256) {
        const float4* kr = (const float4*)(KG + (size_t)k * DMODEL + hoff);
        float s0 = 0, s1 = 0, s2 = 0, s3 = 0;
#pragma unroll
        for (int d4 = 0; d4 < 16; d4++) {
            float4 kv = kr[d4];
            s0 += qv[d4 * 4 + 0] * kv.x;
            s1 += qv[d4 * 4 + 1] * kv.y;
            s2 += qv[d4 * 4 + 2] * kv.z;
            s3 += qv[d4 * 4 + 3] * kv.w;
        }
        float s = (s0 + s1) + (s2 + s3);
        sc[k] = s;
        lmax = fmaxf(lmax, s);
    }
    red[t] = lmax; __syncthreads();
    for (int st = 128; st > 0; st >>= 1) {
        if (t < st) red[t] = fmaxf(red[t], red[t + st]);
        __syncthreads();
    }
    float mx = red[0];
    __syncthreads();
    float lsum = 0.f;
    for (int k = t; k < SEQ; k += 256) {
        float e = __expf(sc[k] - mx);
        sc[k] = e;
        lsum += e;
    }
    red[t] = lsum; __syncthreads();
    for (int st = 128; st > 0; st >>= 1) {
        if (t < st) red[t] += red[t + st];
        __syncthreads();
    }
    float inv = 1.0f / red[0];
    __syncthreads();
    if (t < 64) {
        float a0 = 0, a1 = 0, a2 = 0, a3 = 0;
        for (int k = 0; k < SEQ; k += 4) {
            a0 += sc[k + 0] * VG[(size_t)(k + 0) * DMODEL + hoff + t];
            a1 += sc[k + 1] * VG[(size_t)(k + 1) * DMODEL + hoff + t];
            a2 += sc[k + 2] * VG[(size_t)(k + 2) * DMODEL + hoff + t];
            a3 += sc[k + 3] * VG[(size_t)(k + 3) * DMODEL + hoff + t];
        }
        O[(size_t)(g * 512) * DMODEL + hoff + t] = ((a0 + a1) + (a2 + a3)) * inv;
    }
}

// ---------------- LayerNorm helpers ---------------------------------------
__device__ __forceinline__ void block_ln(
    float* buf, float* red, const float* __restrict__ s,
    const float* __restrict__ b, float* __restrict__ out)
{
    const int t = threadIdx.x;
    float ls = 0.f;
    for (int i = t; i < DMODEL; i += 256) ls += buf[i];
    red[t] = ls; __syncthreads();
    for (int st = 128; st > 0; st >>= 1) {
        if (t < st) red[t] += red[t + st];
        __syncthreads();
    }
    float mean = red[0] * (1.0f / DMODEL);
    __syncthreads();
    float lv = 0.f;
    for (int i = t; i < DMODEL; i += 256) {
        float d = buf[i] - mean;
        lv += d * d;
    }
    red[t] = lv; __syncthreads();
    for (int st = 128; st > 0; st >>= 1) {
        if (t < st) red[t] += red[t + st];
        __syncthreads();
    }
    float inv = rsqrtf(red[0] * (1.0f / DMODEL) + 1e-5f);
    for (int i = t; i < DMODEL; i += 256)
        out[i] = (buf[i] - mean) * inv * s[i] + b[i];
}

__global__ __launch_bounds__(256) void embed_ln_k(
    const int* __restrict__ x, const float* __restrict__ we,
    const float* __restrict__ pe, const float* __restrict__ s,
    const float* __restrict__ b, float* __restrict__ h)
{
    const int p = blockIdx.x;
    const int w = p >> 9, off = p & 511;
    const int id = (off == 0) ? 0 : x[w * 511 + off - 1];
    __shared__ float buf[DMODEL];
    __shared__ float red[256];
    for (int i = threadIdx.x; i < DMODEL; i += 256)
        buf[i] = we[(size_t)id * DMODEL + i] + pe[(size_t)p * DMODEL + i];
    __syncthreads();
    block_ln(buf, red, s, b, h + (size_t)p * DMODEL);
}

__global__ __launch_bounds__(256) void add_ln_k(
    float* __restrict__ h, const float* __restrict__ y,
    const float* __restrict__ s, const float* __restrict__ b)
{
    const int p = blockIdx.x;
    __shared__ float buf[DMODEL];
    __shared__ float red[256];
    for (int i = threadIdx.x; i < DMODEL; i += 256)
        buf[i] = h[(size_t)p * DMODEL + i] + y[(size_t)p * DMODEL + i];
    __syncthreads();
    block_ln(buf, red, s, b, h + (size_t)p * DMODEL);
}

// ---------------- driver ---------------------------------------------------
extern "C" void kernel_launch(void* const* d_in, const int* in_sizes, int n_in,
                              void* d_out, int out_size)
{
    const int*   x    = (const int*)d_in[0];
    const float* we   = (const float*)d_in[1];
    const float* pe   = (const float*)d_in[2];
    const float* els  = (const float*)d_in[3];
    const float* elb  = (const float*)d_in[4];
    const float* Wq   = (const float*)d_in[5];
    const float* bq   = (const float*)d_in[6];
    const float* Wk   = (const float*)d_in[7];
    const float* bk   = (const float*)d_in[8];
    const float* Wv   = (const float*)d_in[9];
    const float* bv   = (const float*)d_in[10];
    const float* Wo   = (const float*)d_in[11];
    const float* bo   = (const float*)d_in[12];
    const float* Wqg  = (const float*)d_in[13];
    const float* bqg  = (const float*)d_in[14];
    const float* Wkg  = (const float*)d_in[15];
    const float* bkg  = (const float*)d_in[16];
    const float* Wvg  = (const float*)d_in[17];
    const float* bvg  = (const float*)d_in[18];
    const float* ln1s = (const float*)d_in[19];
    const float* ln1b = (const float*)d_in[20];
    const float* W1   = (const float*)d_in[21];
    const float* b1   = (const float*)d_in[22];
    const float* W2   = (const float*)d_in[23];
    const float* b2   = (const float*)d_in[24];
    const float* ln2s = (const float*)d_in[25];
    const float* ln2b = (const float*)d_in[26];
    const float* Wout = (const float*)d_in[27];
    const float* bout = (const float*)d_in[28];

    float *h, *q, *k, *v, *kg, *vg, *ao, *y, *tb, *qg;
    cudaGetSymbolAddress((void**)&h,  g_h);
    cudaGetSymbolAddress((void**)&q,  g_q);
    cudaGetSymbolAddress((void**)&k,  g_k);
    cudaGetSymbolAddress((void**)&v,  g_v);
    cudaGetSymbolAddress((void**)&kg, g_kg);
    cudaGetSymbolAddress((void**)&vg, g_vg);
    cudaGetSymbolAddress((void**)&ao, g_ao);
    cudaGetSymbolAddress((void**)&y,  g_y);
    cudaGetSymbolAddress((void**)&tb, g_t);
    cudaGetSymbolAddress((void**)&qg, g_qg);

    embed_ln_k<<<SEQ, 256>>>(x, we, pe, els, elb, h);

    dim3 gQKV(6, 32, 5);  // N=768, M=4096, 5 projections
    dim3 gA(6, 32);       // N=768,  M=4096
    dim3 gF1(24, 32);     // N=3072, M=4096
    for (int l = 0; l < NLAYER; l++) {
        size_t wofs = (size_t)l * DMODEL * DMODEL;
        size_t bofs = (size_t)l * DMODEL;

        Ptrs5 p5;
        p5.W[0] = Wq  + wofs; p5.b[0] = bq  + bofs; p5.C[0] = q;
        p5.W[1] = Wk  + wofs; p5.b[1] = bk  + bofs; p5.C[1] = k;
        p5.W[2] = Wv  + wofs; p5.b[2] = bv  + bofs; p5.C[2] = v;
        p5.W[3] = Wkg + wofs; p5.b[3] = bkg + bofs; p5.C[3] = kg;
        p5.W[4] = Wvg + wofs; p5.b[4] = bvg + bofs; p5.C[4] = vg;
        gemm_qkv5_k<<<gQKV, 256>>>(h, p5, SEQ, DMODEL, DMODEL);
        gemm_rows_k<<<dim3(8, 6), 128>>>(h, Wqg + wofs, bqg + bofs, qg, DMODEL);

        local_attn_k<<<dim3(16, 12), 256>>>(q, k, v, ao);
        global_attn_k<<<dim3(8, 12), 256>>>(qg, kg, vg, ao);

        gemm_tf32_k<0><<<gA, 256>>>(ao, Wo + wofs, bo + bofs, y, SEQ, DMODEL, DMODEL);
        add_ln_k<<<SEQ, 256>>>(h, y, ln1s + bofs, ln1b + bofs);

        gemm_tf32_k<1><<<gF1, 256>>>(h,  W1 + (size_t)l * DMODEL * FFDIM,
                                     b1 + (size_t)l * FFDIM, tb, SEQ, FFDIM, DMODEL);
        gemm_tf32_k<0><<<gA, 256>>>(tb, W2 + (size_t)l * FFDIM * DMODEL,
                                    b2 + bofs, y, SEQ, DMODEL, FFDIM);
        add_ln_k<<<SEQ, 256>>>(h, y, ln2s + bofs, ln2b + bofs);
    }

    gemm_rows_k<<<dim3(8, 1), 128>>>(h, Wout, bout, (float*)d_out, 128);
}